// round 9
// baseline (speedup 1.0000x reference)
#include <cuda_runtime.h>

// img: [256, 3, 224, 224] f32, y_idx/x_idx: [256] i32.
// out[b,c,h,w] = img * (0 if h in [y,y+32) && w in [x,x+32) else 1)
//
// Engine split: the bulk copy (147 MB) goes through the COPY ENGINE via
// cudaMemcpyAsync D2D (explicitly allowed under graph capture), then a tiny
// fixup kernel zeroes only the square regions (256*3*32 row-segments of
// 128 B = 3.1 MB of stores). CE handles pure 1:1 R/W streams at higher HBM
// efficiency than the SM LDG/STG path, which plateaued at ~6.1 TB/s.

#define SQ 32
#define BATCH 256
#define CH 3
#define HH 224
#define WW 224
#define TOTAL_ELEMS (BATCH * CH * HH * WW)

// One warp per (b, c, row-of-square): zero 32 contiguous floats.
// Segments: 256 * 3 * 32 = 24576. 8 warps per CTA -> 3072 CTAs.
#define SEGS (BATCH * CH * SQ)
#define WARPS_PER_CTA 8
#define FIX_THREADS (WARPS_PER_CTA * 32)
#define FIX_BLOCKS (SEGS / WARPS_PER_CTA)

__global__ __launch_bounds__(FIX_THREADS)
void zero_squares_kernel(float* __restrict__ out,
                         const int* __restrict__ y_idx,
                         const int* __restrict__ x_idx) {
    const int warp = blockIdx.x * WARPS_PER_CTA + (threadIdx.x >> 5);
    const int lane = threadIdx.x & 31;

    // warp -> (b, c, r)
    const int r  = warp & (SQ - 1);          // 0..31
    const int bc = warp >> 5;                // 0..767
    const int c  = bc % CH;
    const int b  = bc / CH;

    const int y = __ldg(&y_idx[b]);
    const int x = __ldg(&x_idx[b]);

    const long off = (((long)b * CH + c) * HH + (y + r)) * WW + x + lane;
    out[off] = 0.0f;
}

extern "C" void kernel_launch(void* const* d_in, const int* in_sizes, int n_in,
                              void* d_out, int out_size) {
    const float* img  = (const float*)d_in[0];
    const int* y_idx  = (const int*)d_in[1];
    const int* x_idx  = (const int*)d_in[2];
    float* out        = (float*)d_out;

    // Bulk copy on the copy engine (graph-capturable D2D async memcpy).
    cudaMemcpyAsync(out, img, (size_t)TOTAL_ELEMS * sizeof(float),
                    cudaMemcpyDeviceToDevice);

    // Fixup: zero the 32x32 square per (batch, channel).
    zero_squares_kernel<<<FIX_BLOCKS, FIX_THREADS>>>(out, y_idx, x_idx);
}